// round 12
// baseline (speedup 1.0000x reference)
#include <cuda_runtime.h>
#include <cuda_bf16.h>
#include <cstdint>

// ---- problem constants (fixed by the dataset) ----
#define NND   16384      // nodes = B*S*NN
#define EDG   262144     // edges
#define DD    128        // hidden dim
#define SS    128        // seq len
#define NNPG  64         // nodes per graph-step
#define LL    6          // layers
#define BCAP  64         // bucket capacity per node (deg ~ Poisson(16))

// ---- scratch (device globals; no allocation allowed) ----
__device__ float g_h[NND * DD];                        // 8 MB hidden state
__device__ float g_qkvs[(size_t)NND * 2 * DD];         // 16 MB q|xr per node (fp32)
__device__ __nv_bfloat16 g_kv[(size_t)NND * 2 * DD];   // 8 MB k|v per node (bf16)
__device__ uint32_t g_Wfrag[24 * 16384];               // 1.5 MB fragment-order tf32 weights
__device__ int   g_cnt[NND];                           // per-node in-degree
__device__ unsigned short g_bucket[NND * BCAP];        // 2 MB src ids per dst node

// =====================================================================
// helpers
// =====================================================================
__device__ __forceinline__ uint32_t f2tf32(float f) {
    uint32_t r;
    asm("cvt.rna.tf32.f32 %0, %1;" : "=r"(r) : "f"(f));
    return r;
}

__device__ __forceinline__ void mma_tf32(float* d, const uint32_t* a, const uint32_t* b) {
    asm("mma.sync.aligned.m16n8k8.row.col.f32.tf32.tf32.f32 "
        "{%0,%1,%2,%3}, {%4,%5,%6,%7}, {%8,%9}, {%0,%1,%2,%3};"
        : "+f"(d[0]), "+f"(d[1]), "+f"(d[2]), "+f"(d[3])
        : "r"(a[0]), "r"(a[1]), "r"(a[2]), "r"(a[3]), "r"(b[0]), "r"(b[1]));
}

// =====================================================================
// k_prep (fused): blocks 0..23 convert weights to fragment-order tf32;
// blocks 24..87 zero g_cnt; blocks 88.. input projection + PE.
// =====================================================================
__global__ void k_prep(const float* __restrict__ Wq, const float* __restrict__ Wk,
                       const float* __restrict__ Wv, const float* __restrict__ Ws,
                       const float* __restrict__ x,  const float* __restrict__ Win,
                       const float* __restrict__ bin, const float* __restrict__ pe) {
    int b = blockIdx.x;
    int tid = threadIdx.x;
    if (b < 24) {
        int l = b >> 2, mat = b & 3;
        const float* W = ((mat == 0) ? Wq : (mat == 1) ? Wk : (mat == 2) ? Wv : Ws)
                       + (size_t)l * 16384;
        uint32_t* out = g_Wfrag + (size_t)b * 16384;
#pragma unroll
        for (int i = 0; i < 16; i++) {
            int e4 = tid + i * 256;            // 0..4095
            int kk = e4 >> 5;                  // 0..127
            int n4 = e4 & 31;
            float4 w = *(const float4*)&W[(size_t)kk * 128 + n4 * 4];
            int ks = kk >> 3, kin = kk & 7;
            float wv[4] = {w.x, w.y, w.z, w.w};
#pragma unroll
            for (int c = 0; c < 4; c++) {
                int n = n4 * 4 + c;
                int nt = n >> 3, npair = nt >> 1;
                int ll = (n & 7) * 4 + (kin & 3);
                int u4 = (ks * 8 + npair) * 32 + ll;
                out[(u4 << 2) + (nt & 1) * 2 + (kin >> 2)] = f2tf32(wv[c]);
            }
        }
    } else if (b < 88) {
        g_cnt[(b - 24) * 256 + tid] = 0;
    } else {
        int idx = (b - 88) * 256 + tid;       // 0 .. NND*DD-1
        int n = idx >> 7;
        int d = idx & 127;
        int s = (n / NNPG) % SS;
        float acc = bin[d] + pe[s * DD + d];
        const float* xr = x + n * 9;
#pragma unroll
        for (int f = 0; f < 9; f++) acc = fmaf(xr[f], Win[f * DD + d], acc);
        g_h[idx] = acc;
    }
}

// =====================================================================
// k_bucket: direct scatter of src ids (ushort) into per-dst buckets.
// =====================================================================
__global__ void k_bucket(const int* __restrict__ src, const int* __restrict__ dst) {
    int e = blockIdx.x * blockDim.x + threadIdx.x;
    if (e < EDG) {
        int d = dst[e];
        int p = atomicAdd(&g_cnt[d], 1);
        g_bucket[d * BCAP + p] = (unsigned short)src[e];
    }
}

// =====================================================================
// Fused QKVS GEMM, tf32 mma.sync (round-6 form: 128-row tile, bcur
// prefetch, B fragments from preconverted g_Wfrag)
// =====================================================================
__global__ __launch_bounds__(256, 2) void k_gemm(
    int layer,
    const float* __restrict__ bq, const float* __restrict__ bk,
    const float* __restrict__ bv, const float* __restrict__ bs)
{
    __shared__ uint32_t sA[2 * 4096];   // 32 KB, double-buffered A

    int mat  = blockIdx.y;
    int row0 = blockIdx.x * 128;
    const float* bias = (mat == 0) ? bq : (mat == 1) ? bk : (mat == 2) ? bv : bs;
    const uint4* Bf = (const uint4*)(g_Wfrag + (size_t)(layer * 4 + mat) * 16384);

    int tid  = threadIdx.x;
    int lane = tid & 31;
    int wid  = tid >> 5;
    int rg   = wid >> 1;
    int cg   = wid & 1;
    int gid  = lane >> 2;
    int tig  = lane & 3;

    float acc[2][8][4];
#pragma unroll
    for (int rt = 0; rt < 2; rt++)
#pragma unroll
        for (int nt = 0; nt < 8; nt++)
#pragma unroll
            for (int c = 0; c < 4; c++) acc[rt][nt][c] = 0.f;

    float4 vA[4];
#pragma unroll
    for (int i = 0; i < 4; i++) {
        int e4 = tid + i * 256;
        int m  = e4 >> 3, kq = e4 & 7;
        vA[i] = *(const float4*)&g_h[(size_t)(row0 + m) * 128 + kq * 4];
    }

    uint4 bcur[4];
#pragma unroll
    for (int p = 0; p < 4; p++)
        bcur[p] = Bf[(cg * 4 + p) * 32 + lane];

#pragma unroll
    for (int q = 0; q < 4; q++) {
        uint32_t* A = sA + (q & 1) * 4096;
#pragma unroll
        for (int i = 0; i < 4; i++) {
            int e4 = tid + i * 256;
            int m  = e4 >> 3, kq = e4 & 7;
            int ksl  = kq >> 1;
            int kin0 = (kq & 1) * 4;
            int r = m & 15, mtile = m >> 4, gd = r & 7;
            int jb = (r >= 8 ? 1 : 0) + (kin0 ? 2 : 0);
            int b4 = (ksl * 8 + mtile) * 32 + gd * 4;
            float vv[4] = {vA[i].x, vA[i].y, vA[i].z, vA[i].w};
#pragma unroll
            for (int c = 0; c < 4; c++)
                A[(((b4 + c) ^ (ksl & 3)) << 2) + jb] = __float_as_uint(vv[c]);
        }
        __syncthreads();

        if (q < 3) {
#pragma unroll
            for (int i = 0; i < 4; i++) {
                int e4 = tid + i * 256;
                int m  = e4 >> 3, kq = e4 & 7;
                vA[i] = *(const float4*)&g_h[(size_t)(row0 + m) * 128 + (q + 1) * 32 + kq * 4];
            }
        }

#pragma unroll
        for (int ksl = 0; ksl < 4; ksl++) {
            int ks = q * 4 + ksl;
            uint4 a0 = ((const uint4*)A)[((ksl * 8 + rg * 2 + 0) * 32 + lane) ^ (ksl & 3)];
            uint4 a1 = ((const uint4*)A)[((ksl * 8 + rg * 2 + 1) * 32 + lane) ^ (ksl & 3)];
            uint4 bn[4];
            if (ks < 15) {
#pragma unroll
                for (int p = 0; p < 4; p++)
                    bn[p] = Bf[((ks + 1) * 8 + cg * 4 + p) * 32 + lane];
            }
#pragma unroll
            for (int p = 0; p < 4; p++) {
                uint32_t b0[2] = {bcur[p].x, bcur[p].y};
                uint32_t b1[2] = {bcur[p].z, bcur[p].w};
                mma_tf32(acc[0][2 * p],     (const uint32_t*)&a0, b0);
                mma_tf32(acc[0][2 * p + 1], (const uint32_t*)&a0, b1);
                mma_tf32(acc[1][2 * p],     (const uint32_t*)&a1, b0);
                mma_tf32(acc[1][2 * p + 1], (const uint32_t*)&a1, b1);
            }
            if (ks < 15) {
#pragma unroll
                for (int p = 0; p < 4; p++) bcur[p] = bn[p];
            }
        }
        __syncthreads();
    }

    bool isf32 = (mat == 0 || mat == 3);
    int off = (mat == 0 || mat == 1) ? 0 : 128;
#pragma unroll
    for (int nt = 0; nt < 8; nt++) {
        int c = cg * 64 + nt * 8 + tig * 2;
        float b0 = bias[c], b1 = bias[c + 1];
#pragma unroll
        for (int rt = 0; rt < 2; rt++) {
            int r = row0 + rg * 32 + rt * 16 + gid;
            float v00 = acc[rt][nt][0] + b0, v01 = acc[rt][nt][1] + b1;
            float v10 = acc[rt][nt][2] + b0, v11 = acc[rt][nt][3] + b1;
            if (isf32) {
                *(float2*)(g_qkvs + (size_t)r * 256 + off + c)       = make_float2(v00, v01);
                *(float2*)(g_qkvs + (size_t)(r + 8) * 256 + off + c) = make_float2(v10, v11);
            } else {
                *(__nv_bfloat162*)(g_kv + (size_t)r * 256 + off + c)       = __floats2bfloat162_rn(v00, v01);
                *(__nv_bfloat162*)(g_kv + (size_t)(r + 8) * 256 + off + c) = __floats2bfloat162_rn(v10, v11);
            }
        }
    }
}

// =====================================================================
// Fused attention: FOUR nodes per warp (one per 8-lane quarter).
// Lane t = lane&7 owns dims {8t..8t+7} U {64+8t..64+8t+7}, i.e. the
// two halves of heads (t>>1) and 4+(t>>1). Per edge the quarter reads
// k/v rows with 4 line-minimal LDG.128. Score partials need one
// shfl_xor(1); exp dedup via even/odd butterfly (8 unique exps/edge).
// Epilogue reductions are 8-lane scope, serving 4 nodes per warp.
// =====================================================================
__global__ __launch_bounds__(256) void k_attn(
    const float* __restrict__ Wb, const float* __restrict__ bb,
    const float* __restrict__ lng, const float* __restrict__ lnb)
{
    int warp = (blockIdx.x * 256 + threadIdx.x) >> 5;   // 0..NND/4-1
    int lane = threadIdx.x & 31;
    int t    = lane & 7;
    int qd   = lane >> 3;
    int gw   = warp * 4 + qd;                            // node id
    int dA0  = t * 8;           // first dim group
    int dB0  = 64 + t * 8;      // second dim group

    const float* qrow = g_qkvs + (size_t)gw * 256;
    __nv_bfloat162 qA[4], qB[4];   // q pairs bf16x2, pre-scaled by 1/4
    {
        float4 a0 = ((const float4*)qrow)[2 * t];
        float4 a1 = ((const float4*)qrow)[2 * t + 1];
        float4 b0 = ((const float4*)qrow)[16 + 2 * t];
        float4 b1 = ((const float4*)qrow)[16 + 2 * t + 1];
        qA[0] = __floats2bfloat162_rn(a0.x * .25f, a0.y * .25f);
        qA[1] = __floats2bfloat162_rn(a0.z * .25f, a0.w * .25f);
        qA[2] = __floats2bfloat162_rn(a1.x * .25f, a1.y * .25f);
        qA[3] = __floats2bfloat162_rn(a1.z * .25f, a1.w * .25f);
        qB[0] = __floats2bfloat162_rn(b0.x * .25f, b0.y * .25f);
        qB[1] = __floats2bfloat162_rn(b0.z * .25f, b0.w * .25f);
        qB[2] = __floats2bfloat162_rn(b1.x * .25f, b1.y * .25f);
        qB[3] = __floats2bfloat162_rn(b1.z * .25f, b1.w * .25f);
    }

    float accA[8] = {0.f, 0.f, 0.f, 0.f, 0.f, 0.f, 0.f, 0.f};
    float accB[8] = {0.f, 0.f, 0.f, 0.f, 0.f, 0.f, 0.f, 0.f};
    float den1 = 0.f, den2 = 0.f;

    int cnt = g_cnt[gw];
    int c2 = max(cnt, __shfl_xor_sync(0xffffffffu, cnt, 8));
    int cntmax = max(c2, __shfl_xor_sync(0xffffffffu, c2, 16));
    const unsigned short* bkt = g_bucket + gw * BCAP;

    for (int base = 0; base < cntmax; base += 8) {
        int id = (base + t < cnt) ? (int)bkt[base + t] : 0;
        int emax = min(8, cntmax - base);
        for (int e = 0; e < emax; e++) {
            bool act = base + e < cnt;
            int s = __shfl_sync(0xffffffffu, id, (lane & 24) | e);
            const uint4* kvrow = (const uint4*)(g_kv + (size_t)s * 256);
            uint4 krA = kvrow[t];
            uint4 krB = kvrow[8 + t];
            uint4 vrA = kvrow[16 + t];
            uint4 vrB = kvrow[24 + t];
            // partial dots in bf16x2
            __nv_bfloat162 sA2 = __hmul2(qA[0], *(const __nv_bfloat162*)&krA.x);
            sA2 = __hfma2(qA[1], *(const __nv_bfloat162*)&krA.y, sA2);
            sA2 = __hfma2(qA[2], *(const __nv_bfloat162*)&krA.z, sA2);
            sA2 = __hfma2(qA[3], *(const __nv_bfloat162*)&krA.w, sA2);
            __nv_bfloat162 sB2 = __hmul2(qB[0], *(const __nv_bfloat162*)&krB.x);
            sB2 = __hfma2(qB[1], *(const __nv_bfloat162*)&krB.y, sB2);
            sB2 = __hfma2(qB[2], *(const __nv_bfloat162*)&krB.z, sB2);
            sB2 = __hfma2(qB[3], *(const __nv_bfloat162*)&krB.w, sB2);
            float2 fA = __bfloat1622float2(sA2);
            float2 fB = __bfloat1622float2(sB2);
            float d1 = fA.x + fA.y;
            float d2 = fB.x + fB.y;
            d1 += __shfl_xor_sync(0xffffffffu, d1, 1);   // full head (t>>1)
            d2 += __shfl_xor_sync(0xffffffffu, d2, 1);   // full head 4+(t>>1)
            // exp dedup: even lane exp(d1), odd lane exp(d2), butterfly
            float scsel = (lane & 1) ? d2 : d1;
            float p = act ? __expf(scsel) : 0.f;
            float po = __shfl_xor_sync(0xffffffffu, p, 1);
            float p1 = (lane & 1) ? po : p;
            float p2 = (lane & 1) ? p : po;
            // v accumulate in fp32
            float2 v0 = __bfloat1622float2(*(const __nv_bfloat162*)&vrA.x);
            float2 v1 = __bfloat1622float2(*(const __nv_bfloat162*)&vrA.y);
            float2 v2 = __bfloat1622float2(*(const __nv_bfloat162*)&vrA.z);
            float2 v3 = __bfloat1622float2(*(const __nv_bfloat162*)&vrA.w);
            accA[0] += p1 * v0.x; accA[1] += p1 * v0.y;
            accA[2] += p1 * v1.x; accA[3] += p1 * v1.y;
            accA[4] += p1 * v2.x; accA[5] += p1 * v2.y;
            accA[6] += p1 * v3.x; accA[7] += p1 * v3.y;
            float2 w0 = __bfloat1622float2(*(const __nv_bfloat162*)&vrB.x);
            float2 w1 = __bfloat1622float2(*(const __nv_bfloat162*)&vrB.y);
            float2 w2 = __bfloat1622float2(*(const __nv_bfloat162*)&vrB.z);
            float2 w3 = __bfloat1622float2(*(const __nv_bfloat162*)&vrB.w);
            accB[0] += p2 * w0.x; accB[1] += p2 * w0.y;
            accB[2] += p2 * w1.x; accB[3] += p2 * w1.y;
            accB[4] += p2 * w2.x; accB[5] += p2 * w2.y;
            accB[6] += p2 * w3.x; accB[7] += p2 * w3.y;
            den1 += p1; den2 += p2;
        }
    }

    float inv1 = 1.f / (den1 + 1e-16f);
    float inv2 = 1.f / (den2 + 1e-16f);
    float agA[8], agB[8];
#pragma unroll
    for (int j = 0; j < 8; j++) { agA[j] = accA[j] * inv1; agB[j] = accB[j] * inv2; }

    float xrA[8], xrB[8];
    {
        float4 a0 = ((const float4*)(qrow + 128))[2 * t];
        float4 a1 = ((const float4*)(qrow + 128))[2 * t + 1];
        float4 b0 = ((const float4*)(qrow + 128))[16 + 2 * t];
        float4 b1 = ((const float4*)(qrow + 128))[16 + 2 * t + 1];
        xrA[0] = a0.x; xrA[1] = a0.y; xrA[2] = a0.z; xrA[3] = a0.w;
        xrA[4] = a1.x; xrA[5] = a1.y; xrA[6] = a1.z; xrA[7] = a1.w;
        xrB[0] = b0.x; xrB[1] = b0.y; xrB[2] = b0.z; xrB[3] = b0.w;
        xrB[4] = b1.x; xrB[5] = b1.y; xrB[6] = b1.z; xrB[7] = b1.w;
    }

    // beta gate: 8-lane reduction within the quarter (offsets 4,2,1)
    float part = 0.f;
#pragma unroll
    for (int j = 0; j < 8; j++) {
        int dA = dA0 + j, dB = dB0 + j;
        part += agA[j] * Wb[dA] + xrA[j] * Wb[128 + dA] + (agA[j] - xrA[j]) * Wb[256 + dA];
        part += agB[j] * Wb[dB] + xrB[j] * Wb[128 + dB] + (agB[j] - xrB[j]) * Wb[256 + dB];
    }
#pragma unroll
    for (int o = 4; o; o >>= 1) part += __shfl_xor_sync(0xffffffffu, part, o);
    float beta = 1.f / (1.f + __expf(-(part + bb[0])));

    float hvA[8], hvB[8];
    {
        const float4* hrow = (const float4*)(g_h + (size_t)gw * 128);
        float4 a0 = hrow[2 * t];
        float4 a1 = hrow[2 * t + 1];
        float4 b0 = hrow[16 + 2 * t];
        float4 b1 = hrow[16 + 2 * t + 1];
        hvA[0] = a0.x; hvA[1] = a0.y; hvA[2] = a0.z; hvA[3] = a0.w;
        hvA[4] = a1.x; hvA[5] = a1.y; hvA[6] = a1.z; hvA[7] = a1.w;
        hvB[0] = b0.x; hvB[1] = b0.y; hvB[2] = b0.z; hvB[3] = b0.w;
        hvB[4] = b1.x; hvB[5] = b1.y; hvB[6] = b1.z; hvB[7] = b1.w;
    }
    float yA[8], yB[8];
#pragma unroll
    for (int j = 0; j < 8; j++) {
        yA[j] = hvA[j] + beta * xrA[j] + (1.f - beta) * agA[j];
        yB[j] = hvB[j] + beta * xrB[j] + (1.f - beta) * agB[j];
    }

    float ssum = 0.f;
#pragma unroll
    for (int j = 0; j < 8; j++) ssum += yA[j] + yB[j];
#pragma unroll
    for (int o = 4; o; o >>= 1) ssum += __shfl_xor_sync(0xffffffffu, ssum, o);
    float mean = ssum * (1.f / 128.f);

    float vs = 0.f;
#pragma unroll
    for (int j = 0; j < 8; j++) {
        float ta = yA[j] - mean; vs += ta * ta;
        float tb = yB[j] - mean; vs += tb * tb;
    }
#pragma unroll
    for (int o = 4; o; o >>= 1) vs += __shfl_xor_sync(0xffffffffu, vs, o);
    float rstd = rsqrtf(vs * (1.f / 128.f) + 1e-5f);

    float4 oA0, oA1, oB0, oB1;
    oA0.x = (yA[0] - mean) * rstd * lng[dA0 + 0] + lnb[dA0 + 0];
    oA0.y = (yA[1] - mean) * rstd * lng[dA0 + 1] + lnb[dA0 + 1];
    oA0.z = (yA[2] - mean) * rstd * lng[dA0 + 2] + lnb[dA0 + 2];
    oA0.w = (yA[3] - mean) * rstd * lng[dA0 + 3] + lnb[dA0 + 3];
    oA1.x = (yA[4] - mean) * rstd * lng[dA0 + 4] + lnb[dA0 + 4];
    oA1.y = (yA[5] - mean) * rstd * lng[dA0 + 5] + lnb[dA0 + 5];
    oA1.z = (yA[6] - mean) * rstd * lng[dA0 + 6] + lnb[dA0 + 6];
    oA1.w = (yA[7] - mean) * rstd * lng[dA0 + 7] + lnb[dA0 + 7];
    oB0.x = (yB[0] - mean) * rstd * lng[dB0 + 0] + lnb[dB0 + 0];
    oB0.y = (yB[1] - mean) * rstd * lng[dB0 + 1] + lnb[dB0 + 1];
    oB0.z = (yB[2] - mean) * rstd * lng[dB0 + 2] + lnb[dB0 + 2];
    oB0.w = (yB[3] - mean) * rstd * lng[dB0 + 3] + lnb[dB0 + 3];
    oB1.x = (yB[4] - mean) * rstd * lng[dB0 + 4] + lnb[dB0 + 4];
    oB1.y = (yB[5] - mean) * rstd * lng[dB0 + 5] + lnb[dB0 + 5];
    oB1.z = (yB[6] - mean) * rstd * lng[dB0 + 6] + lnb[dB0 + 6];
    oB1.w = (yB[7] - mean) * rstd * lng[dB0 + 7] + lnb[dB0 + 7];
    float4* hout = (float4*)(g_h + (size_t)gw * 128);
    hout[2 * t]          = oA0;
    hout[2 * t + 1]      = oA1;
    hout[16 + 2 * t]     = oB0;
    hout[16 + 2 * t + 1] = oB1;
}

// =====================================================================
// Output head: out = relu(h @ Wo1 + bo1) @ Wo2 + bo2    (16 nodes / block)
// =====================================================================
__global__ __launch_bounds__(256) void k_out(
    const float* __restrict__ Wo1, const float* __restrict__ bo1,
    const float* __restrict__ Wo2, const float* __restrict__ bo2,
    float* __restrict__ out)
{
    __shared__ float w1[128 * 64];
    __shared__ float hs[16][128];
    __shared__ float ts[16][64];
    int tid = threadIdx.x;
    int n0 = blockIdx.x * 16;

    for (int i = tid; i < 128 * 64 / 4; i += 256)
        ((float4*)w1)[i] = ((const float4*)Wo1)[i];
    for (int i = tid; i < 16 * 128 / 4; i += 256)
        ((float4*)&hs[0][0])[i] = ((const float4*)(g_h + (size_t)n0 * 128))[i];
    __syncthreads();

    int j = tid & 63, g0 = tid >> 6;
    float a0 = bo1[j], a1 = a0, a2 = a0, a3 = a0;
#pragma unroll 8
    for (int d = 0; d < 128; d++) {
        float w = w1[d * 64 + j];
        a0 = fmaf(hs[g0 +  0][d], w, a0);
        a1 = fmaf(hs[g0 +  4][d], w, a1);
        a2 = fmaf(hs[g0 +  8][d], w, a2);
        a3 = fmaf(hs[g0 + 12][d], w, a3);
    }
    ts[g0 +  0][j] = fmaxf(a0, 0.f);
    ts[g0 +  4][j] = fmaxf(a1, 0.f);
    ts[g0 +  8][j] = fmaxf(a2, 0.f);
    ts[g0 + 12][j] = fmaxf(a3, 0.f);
    __syncthreads();

    if (tid < 48) {
        int n = tid / 3, c = tid % 3;
        float o = bo2[c];
#pragma unroll
        for (int k = 0; k < 64; k++) o = fmaf(ts[n][k], Wo2[k * 3 + c], o);
        out[(size_t)(n0 + n) * 3 + c] = o;
    }
}

// =====================================================================
// launcher  (k_attn layer0 in the ncu-captured 4th slot:
//            k_prep, k_gemm, k_bucket, k_attn, ...)
// =====================================================================
extern "C" void kernel_launch(void* const* d_in, const int* in_sizes, int n_in,
                              void* d_out, int out_size)
{
    const float* x    = (const float*)d_in[0];
    const int*   ei   = (const int*)  d_in[1];
    const float* pe   = (const float*)d_in[2];
    const float* Win  = (const float*)d_in[3];
    const float* bin  = (const float*)d_in[4];
    const float* Wq   = (const float*)d_in[5];
    const float* bq   = (const float*)d_in[6];
    const float* Wk   = (const float*)d_in[7];
    const float* bk   = (const float*)d_in[8];
    const float* Wv   = (const float*)d_in[9];
    const float* bv   = (const float*)d_in[10];
    const float* Ws   = (const float*)d_in[11];
    const float* bs   = (const float*)d_in[12];
    const float* Wb   = (const float*)d_in[13];
    const float* bb   = (const float*)d_in[14];
    const float* lng  = (const float*)d_in[15];
    const float* lnb  = (const float*)d_in[16];
    const float* Wo1  = (const float*)d_in[17];
    const float* bo1  = (const float*)d_in[18];
    const float* Wo2  = (const float*)d_in[19];
    const float* bo2  = (const float*)d_in[20];
    float* out = (float*)d_out;

    const int* src = ei;
    const int* dst = ei + EDG;

    // 1: fused weights-conversion + cnt-zero + input projection
    k_prep<<<88 + NND * DD / 256, 256>>>(Wq, Wk, Wv, Ws, x, Win, bin, pe);

    // 2: layer-0 GEMM
    dim3 gg(NND / 128, 4);
    k_gemm<<<gg, 256>>>(0, bq, bk, bv, bs);

    // 3: edge bucket scatter (ushort ids)
    k_bucket<<<EDG / 256, 256>>>(src, dst);

    // 4: layer-0 attention -> ncu-captured slot (4 nodes per warp)
    k_attn<<<NND / 32, 256>>>(Wb, bb, lng, lnb);

    for (int l = 1; l < LL; l++) {
        k_gemm<<<gg, 256>>>(l, bq + l * DD, bk + l * DD, bv + l * DD, bs + l * DD);
        k_attn<<<NND / 32, 256>>>(Wb + l * 384, bb + l, lng + l * DD, lnb + l * DD);
    }

    k_out<<<NND / 16, 256>>>(Wo1, bo1, Wo2, bo2, out);
}